// round 1
// baseline (speedup 1.0000x reference)
#include <cuda_runtime.h>
#include <math.h>

#define S_    1024
#define H_    1024
#define NH_   16
#define KVH_  4
#define HD_   64
#define REP_  4
#define E_    64
#define TOPK_ 8
#define ID_   1408
#define CAP_  256
#define EPS_  1e-6f

// ---------------- scratch (device globals; no allocations allowed) ----------
__device__ float g_xn1 [S_ * H_];
__device__ float g_qbuf[S_ * NH_ * HD_];
__device__ float g_kbuf[S_ * KVH_ * HD_];
__device__ float g_vbuf[S_ * KVH_ * HD_];
__device__ float g_qr  [NH_ * S_ * HD_];
__device__ float g_kr  [KVH_ * S_ * HD_];
__device__ float g_vr  [KVH_ * S_ * HD_];
__device__ float g_sc  [(long)NH_ * S_ * S_];     // 64 MB scores/probs
__device__ float g_aoh [NH_ * S_ * HD_];
__device__ float g_ao  [S_ * H_];
__device__ float g_hres[S_ * H_];
__device__ float g_xn2 [S_ * H_];
__device__ float g_logits[S_ * E_];
__device__ int   g_topi[S_ * TOPK_];
__device__ float g_coef[S_ * TOPK_];
__device__ int   g_pos [S_ * TOPK_];
__device__ float g_buf [(long)E_ * CAP_ * H_];    // 64 MB
__device__ float g_gg  [(long)E_ * CAP_ * ID_];   // 92 MB
__device__ float g_uu  [(long)E_ * CAP_ * ID_];   // 92 MB
__device__ float g_yy  [(long)E_ * CAP_ * H_];    // 64 MB
__device__ float g_sg  [S_ * ID_];
__device__ float g_su  [S_ * ID_];
__device__ float g_shb [S_ * H_];

// ---------------- reductions ----------------
__device__ __forceinline__ float warpSum(float v) {
    #pragma unroll
    for (int o = 16; o; o >>= 1) v += __shfl_xor_sync(0xffffffffu, v, o);
    return v;
}
__device__ __forceinline__ float warpMax(float v) {
    #pragma unroll
    for (int o = 16; o; o >>= 1) v = fmaxf(v, __shfl_xor_sync(0xffffffffu, v, o));
    return v;
}
__device__ float blockSum(float v) {
    __shared__ float sh[32];
    __shared__ float tot;
    int lane = threadIdx.x & 31, wid = threadIdx.x >> 5;
    v = warpSum(v);
    if (lane == 0) sh[wid] = v;
    __syncthreads();
    int nw = (blockDim.x + 31) >> 5;
    float w = (threadIdx.x < nw) ? sh[threadIdx.x] : 0.f;
    if (wid == 0) {
        w = warpSum(w);
        if (lane == 0) tot = w;
    }
    __syncthreads();
    float r = tot;
    __syncthreads();
    return r;
}
__device__ float blockMax(float v) {
    __shared__ float sh[32];
    __shared__ float tot;
    int lane = threadIdx.x & 31, wid = threadIdx.x >> 5;
    v = warpMax(v);
    if (lane == 0) sh[wid] = v;
    __syncthreads();
    int nw = (blockDim.x + 31) >> 5;
    float w = (threadIdx.x < nw) ? sh[threadIdx.x] : -1e30f;
    if (wid == 0) {
        w = warpMax(w);
        if (lane == 0) tot = w;
    }
    __syncthreads();
    float r = tot;
    __syncthreads();
    return r;
}

// ---------------- generic tiled SGEMM (batched, optional B-transpose) -------
template<int BM, int BN, int BK, int TM, int TN, bool TB>
__global__ void sgemm_k(const float* __restrict__ A, const float* __restrict__ B,
                        float* __restrict__ C, int M, int N, int K,
                        long sA, long sB, long sC, int bDiv)
{
    const int tid = threadIdx.x;
    const int bz  = blockIdx.z;
    A += (long)bz * sA;
    B += (long)(bz / bDiv) * sB;
    C += (long)bz * sC;
    const int row0 = blockIdx.y * BM;
    const int col0 = blockIdx.x * BN;

    __shared__ float As[BK][BM + 4];
    __shared__ float Bs[BK][BN + 4];

    float acc[TM][TN];
    #pragma unroll
    for (int i = 0; i < TM; i++)
        #pragma unroll
        for (int j = 0; j < TN; j++) acc[i][j] = 0.f;

    const int tRow = (tid / (BN / TN)) * TM;
    const int tCol = (tid % (BN / TN)) * TN;

    const int aRow = tid / (BK / 4);
    const int aK   = (tid % (BK / 4)) * 4;

    int bR, bC;
    if (TB) { bR = tid / (BK / 4); bC = (tid % (BK / 4)) * 4; }   // bR = n, bC = k
    else    { bR = tid / (BN / 4); bC = (tid % (BN / 4)) * 4; }   // bR = k, bC = n

    for (int k0 = 0; k0 < K; k0 += BK) {
        // ---- A tile ----
        {
            int gr = row0 + aRow;
            int gk = k0 + aK;
            float4 v = make_float4(0.f, 0.f, 0.f, 0.f);
            if (gr < M) {
                if (gk + 3 < K) v = *reinterpret_cast<const float4*>(A + (long)gr * K + gk);
                else {
                    float* pv = (float*)&v;
                    for (int j = 0; j < 4; j++) if (gk + j < K) pv[j] = A[(long)gr * K + gk + j];
                }
            }
            As[aK + 0][aRow] = v.x; As[aK + 1][aRow] = v.y;
            As[aK + 2][aRow] = v.z; As[aK + 3][aRow] = v.w;
        }
        // ---- B tile ----
        if (TB) {
            int gn = col0 + bR;
            int gk = k0 + bC;
            float4 v = make_float4(0.f, 0.f, 0.f, 0.f);
            if (gn < N) {
                if (gk + 3 < K) v = *reinterpret_cast<const float4*>(B + (long)gn * K + gk);
                else {
                    float* pv = (float*)&v;
                    for (int j = 0; j < 4; j++) if (gk + j < K) pv[j] = B[(long)gn * K + gk + j];
                }
            }
            Bs[bC + 0][bR] = v.x; Bs[bC + 1][bR] = v.y;
            Bs[bC + 2][bR] = v.z; Bs[bC + 3][bR] = v.w;
        } else {
            int gk = k0 + bR;
            int gn = col0 + bC;
            float4 v = make_float4(0.f, 0.f, 0.f, 0.f);
            if (gk < K) {
                if (gn + 3 < N) v = *reinterpret_cast<const float4*>(B + (long)gk * N + gn);
                else {
                    float* pv = (float*)&v;
                    for (int j = 0; j < 4; j++) if (gn + j < N) pv[j] = B[(long)gk * N + gn + j];
                }
            }
            *reinterpret_cast<float4*>(&Bs[bR][bC]) = v;
        }
        __syncthreads();
        #pragma unroll
        for (int k = 0; k < BK; k++) {
            float rA[TM], rB[TN];
            #pragma unroll
            for (int m = 0; m < TM; m++) rA[m] = As[k][tRow + m];
            #pragma unroll
            for (int n = 0; n < TN; n++) rB[n] = Bs[k][tCol + n];
            #pragma unroll
            for (int m = 0; m < TM; m++)
                #pragma unroll
                for (int n = 0; n < TN; n++) acc[m][n] += rA[m] * rB[n];
        }
        __syncthreads();
    }
    #pragma unroll
    for (int m = 0; m < TM; m++) {
        int gr = row0 + tRow + m;
        if (gr >= M) continue;
        #pragma unroll
        for (int n = 0; n < TN; n++) {
            int gc = col0 + tCol + n;
            if (gc < N) C[(long)gr * N + gc] = acc[m][n];
        }
    }
}

// ---------------- elementwise / small kernels ----------------
__global__ void rmsnorm_k(const float* __restrict__ x, const float* __restrict__ w,
                          float* __restrict__ y)
{
    int t = blockIdx.x;
    const float* xr = x + (long)t * H_;
    float s = 0.f;
    for (int i = threadIdx.x; i < H_; i += blockDim.x) { float v = xr[i]; s += v * v; }
    s = blockSum(s);
    float inv = rsqrtf(s / (float)H_ + EPS_);
    for (int i = threadIdx.x; i < H_; i += blockDim.x)
        y[(long)t * H_ + i] = xr[i] * inv * w[i];
}

// src (S, nh*HD) row-major -> dst (nh, S, HD) with RoPE applied
__global__ void rope_k(const float* __restrict__ src, float* __restrict__ dst, int nh)
{
    int idx = blockIdx.x * blockDim.x + threadIdx.x;
    int total = nh * S_ * HD_;
    if (idx >= total) return;
    int d = idx % HD_;
    int s = (idx / HD_) % S_;
    int h = idx / (HD_ * S_);
    const float* p = src + (long)s * (nh * HD_) + h * HD_;
    float v  = p[d];
    float pr = (d < HD_ / 2) ? -p[d + HD_ / 2] : p[d - HD_ / 2];
    int i = d & (HD_ / 2 - 1);
    float inv = expf(-(float)i * (9.210340371976184f / (HD_ / 2)));  // 10000^(-i/32)
    float ang = (float)s * inv;
    float sn, cs;
    sincosf(ang, &sn, &cs);
    dst[((long)h * S_ + s) * HD_ + d] = v * cs + pr * sn;
}

// src (S, nh*HD) -> dst (nh, S, HD) (no rope, for V)
__global__ void transpose_heads_k(const float* __restrict__ src, float* __restrict__ dst, int nh)
{
    int idx = blockIdx.x * blockDim.x + threadIdx.x;
    int total = nh * S_ * HD_;
    if (idx >= total) return;
    int d = idx % HD_;
    int s = (idx / HD_) % S_;
    int h = idx / (HD_ * S_);
    dst[((long)h * S_ + s) * HD_ + d] = src[(long)s * nh * HD_ + h * HD_ + d];
}

// dst (S, nh*HD) <- src (nh, S, HD)
__global__ void merge_heads_k(const float* __restrict__ src, float* __restrict__ dst)
{
    int idx = blockIdx.x * blockDim.x + threadIdx.x;
    int total = NH_ * S_ * HD_;
    if (idx >= total) return;
    int d = idx % HD_;
    int s = (idx / HD_) % S_;
    int h = idx / (HD_ * S_);
    dst[(long)s * H_ + h * HD_ + d] = src[((long)h * S_ + s) * HD_ + d];
}

__global__ void softmax_k(float* __restrict__ sc, const float* __restrict__ mask)
{
    int r = blockIdx.x, h = blockIdx.y;
    float* row = sc + ((long)h * S_ + r) * S_;
    const float* mr = mask + (long)r * S_;
    float mx = -1e30f;
    for (int j = threadIdx.x; j < S_; j += blockDim.x) {
        float v = row[j] * 0.125f + mr[j];  // 1/sqrt(64)
        row[j] = v;
        mx = fmaxf(mx, v);
    }
    mx = blockMax(mx);
    float sum = 0.f;
    for (int j = threadIdx.x; j < S_; j += blockDim.x) {
        float e = expf(row[j] - mx);
        row[j] = e;
        sum += e;
    }
    sum = blockSum(sum);
    float inv = 1.f / sum;
    for (int j = threadIdx.x; j < S_; j += blockDim.x) row[j] *= inv;
}

__global__ void add_k(const float* __restrict__ a, const float* __restrict__ b,
                      float* __restrict__ c, long n)
{
    long i = (long)blockIdx.x * blockDim.x + threadIdx.x;
    if (i < n) c[i] = a[i] + b[i];
}

__global__ void zero_k(float* __restrict__ p, long n4)
{
    long i = (long)blockIdx.x * blockDim.x + threadIdx.x;
    if (i < n4) reinterpret_cast<float4*>(p)[i] = make_float4(0.f, 0.f, 0.f, 0.f);
}

__global__ void topk_k(const float* __restrict__ logits, int* __restrict__ topi,
                       float* __restrict__ coef)
{
    int t = blockIdx.x * blockDim.x + threadIdx.x;
    if (t >= S_) return;
    const float* lr = logits + (long)t * E_;
    unsigned long long sel = 0ull;
    float tv[TOPK_];
    int   ti[TOPK_];
    for (int k = 0; k < TOPK_; k++) {
        float best = -1e30f; int bi = 0;
        for (int e = 0; e < E_; e++) {
            if ((sel >> e) & 1ull) continue;
            float v = lr[e];
            if (v > best) { best = v; bi = e; }
        }
        sel |= 1ull << bi;
        tv[k] = best; ti[k] = bi;
    }
    float mx = tv[0];
    float ex[TOPK_]; float sum = 0.f;
    for (int k = 0; k < TOPK_; k++) { ex[k] = expf(tv[k] - mx); sum += ex[k]; }
    float inv = 1.f / sum;
    for (int k = 0; k < TOPK_; k++) { topi[t * TOPK_ + k] = ti[k]; coef[t * TOPK_ + k] = ex[k] * inv; }
}

// per-expert occurrence-order position assignment (matches cumsum-of-one-hot)
__global__ void assign_k(const int* __restrict__ topi, int* __restrict__ pos)
{
    const int e = blockIdx.x;           // expert
    const int NTOT = S_ * TOPK_;        // 8192
    __shared__ int sdata[256];
    int base = 0;
    for (int chunk = 0; chunk < NTOT; chunk += 256) {
        int i = chunk + threadIdx.x;
        int p = (topi[i] == e) ? 1 : 0;
        sdata[threadIdx.x] = p;
        __syncthreads();
        #pragma unroll
        for (int off = 1; off < 256; off <<= 1) {
            int v = (threadIdx.x >= off) ? sdata[threadIdx.x - off] : 0;
            __syncthreads();
            sdata[threadIdx.x] += v;
            __syncthreads();
        }
        if (p) pos[i] = base + sdata[threadIdx.x] - 1;
        base += sdata[255];
        __syncthreads();
    }
}

__global__ void scatter_k(const float* __restrict__ xn2, const int* __restrict__ topi,
                          const int* __restrict__ pos, float* __restrict__ buf)
{
    int i = blockIdx.x;                 // 0..8191
    int p = pos[i];
    if (p >= CAP_) return;
    int e = topi[i];
    int t = i >> 3;
    const float4* src = reinterpret_cast<const float4*>(xn2 + (long)t * H_);
    float4* dst = reinterpret_cast<float4*>(buf + ((long)e * CAP_ + p) * H_);
    dst[threadIdx.x] = src[threadIdx.x];   // 256 threads x float4 = 1024 floats
}

__global__ void act_k(float* __restrict__ g, const float* __restrict__ u, long n)
{
    long i = (long)blockIdx.x * blockDim.x + threadIdx.x;
    if (i < n) {
        float x = g[i];
        g[i] = (x / (1.f + expf(-x))) * u[i];
    }
}

__global__ void final_k(const float* __restrict__ hres, const float* __restrict__ shb,
                        const float* __restrict__ y, const int* __restrict__ topi,
                        const int* __restrict__ pos, const float* __restrict__ coef,
                        float* __restrict__ out)
{
    int t = blockIdx.x;
    int j = threadIdx.x;                // 256 float4 lanes per token
    float4 a = reinterpret_cast<const float4*>(hres)[(long)t * 256 + j];
    float4 b = reinterpret_cast<const float4*>(shb)[(long)t * 256 + j];
    a.x += b.x; a.y += b.y; a.z += b.z; a.w += b.w;
    #pragma unroll
    for (int k = 0; k < TOPK_; k++) {
        int idx = t * TOPK_ + k;
        int p = pos[idx];
        if (p < CAP_) {
            int e = topi[idx];
            float c = coef[idx];
            float4 v = reinterpret_cast<const float4*>(y)[((long)e * CAP_ + p) * 256 + j];
            a.x += c * v.x; a.y += c * v.y; a.z += c * v.z; a.w += c * v.w;
        }
    }
    reinterpret_cast<float4*>(out)[(long)t * 256 + j] = a;
}

// ---------------- host-side launchers ----------------
static void gemmA(const float* A, const float* B, float* C, int M, int N, int K,
                  int batch, long sA, long sB, long sC, int bDiv, cudaStream_t st)
{
    dim3 grid((N + 127) / 128, (M + 127) / 128, batch);
    sgemm_k<128, 128, 8, 8, 8, false><<<grid, 256, 0, st>>>(A, B, C, M, N, K, sA, sB, sC, bDiv);
}
static void gemmB_nn(const float* A, const float* B, float* C, int M, int N, int K,
                     int batch, long sA, long sB, long sC, int bDiv, cudaStream_t st)
{
    dim3 grid((N + 63) / 64, (M + 63) / 64, batch);
    sgemm_k<64, 64, 16, 4, 4, false><<<grid, 256, 0, st>>>(A, B, C, M, N, K, sA, sB, sC, bDiv);
}
static void gemmB_nt(const float* A, const float* B, float* C, int M, int N, int K,
                     int batch, long sA, long sB, long sC, int bDiv, cudaStream_t st)
{
    dim3 grid((N + 63) / 64, (M + 63) / 64, batch);
    sgemm_k<64, 64, 16, 4, 4, true><<<grid, 256, 0, st>>>(A, B, C, M, N, K, sA, sB, sC, bDiv);
}

extern "C" void kernel_launch(void* const* d_in, const int* in_sizes, int n_in,
                              void* d_out, int out_size)
{
    (void)in_sizes; (void)n_in; (void)out_size;
    cudaStream_t st = 0;

    const float* x     = (const float*)d_in[0];   // hidden_states (1,1024,1024)
    const float* mask  = (const float*)d_in[1];   // (1,1,1024,1024)
    const float* wln1  = (const float*)d_in[2];
    const float* wln2  = (const float*)d_in[3];
    const float* Wq    = (const float*)d_in[4];
    const float* Wk    = (const float*)d_in[5];
    const float* Wv    = (const float*)d_in[6];
    const float* Wo    = (const float*)d_in[7];
    const float* Wgate = (const float*)d_in[8];
    const float* Weg   = (const float*)d_in[9];
    const float* Weu   = (const float*)d_in[10];
    const float* Wed   = (const float*)d_in[11];
    const float* Wsg   = (const float*)d_in[12];
    const float* Wsu   = (const float*)d_in[13];
    const float* Wsd   = (const float*)d_in[14];
    float* out = (float*)d_out;

    void *p;
    #define GET(sym, var) cudaGetSymbolAddress(&p, sym); float* var = (float*)p;
    #define GETI(sym, var) cudaGetSymbolAddress(&p, sym); int* var = (int*)p;
    GET(g_xn1, xn1)  GET(g_qbuf, qbuf) GET(g_kbuf, kbuf) GET(g_vbuf, vbuf)
    GET(g_qr, qr)    GET(g_kr, kr)     GET(g_vr, vr)     GET(g_sc, sc)
    GET(g_aoh, aoh)  GET(g_ao, ao)     GET(g_hres, hres) GET(g_xn2, xn2)
    GET(g_logits, logits) GET(g_coef, coef)
    GET(g_buf, buf)  GET(g_gg, gg)     GET(g_uu, uu)     GET(g_yy, yy)
    GET(g_sg, sg)    GET(g_su, su)     GET(g_shb, shb)
    GETI(g_topi, topi) GETI(g_pos, pos)
    #undef GET
    #undef GETI

    // ===== attention =====
    rmsnorm_k<<<S_, 256, 0, st>>>(x, wln1, xn1);

    gemmA(xn1, Wq, qbuf, S_, NH_ * HD_, H_, 1, 0, 0, 0, 1, st);
    gemmA(xn1, Wk, kbuf, S_, KVH_ * HD_, H_, 1, 0, 0, 0, 1, st);
    gemmA(xn1, Wv, vbuf, S_, KVH_ * HD_, H_, 1, 0, 0, 0, 1, st);

    {
        int totq = NH_ * S_ * HD_, totk = KVH_ * S_ * HD_;
        rope_k<<<(totq + 255) / 256, 256, 0, st>>>(qbuf, qr, NH_);
        rope_k<<<(totk + 255) / 256, 256, 0, st>>>(kbuf, kr, KVH_);
        transpose_heads_k<<<(totk + 255) / 256, 256, 0, st>>>(vbuf, vr, KVH_);
    }

    // scores[h] = qr[h] @ kr[h/4]^T    (16 x 1024x1024, K=64)
    gemmB_nt(qr, kr, sc, S_, S_, HD_, NH_,
             (long)S_ * HD_, (long)S_ * HD_, (long)S_ * S_, REP_, st);

    softmax_k<<<dim3(S_, NH_), 256, 0, st>>>(sc, mask);

    // aoh[h] = probs[h] @ vr[h/4]      (16 x 1024x64, K=1024)
    gemmB_nn(sc, vr, aoh, S_, HD_, S_, NH_,
             (long)S_ * S_, (long)S_ * HD_, (long)S_ * HD_, REP_, st);

    merge_heads_k<<<(NH_ * S_ * HD_ + 255) / 256, 256, 0, st>>>(aoh, ao);

    gemmA(ao, Wo, xn1 /*reuse as attn_proj*/, S_, H_, H_, 1, 0, 0, 0, 1, st);
    add_k<<<(S_ * H_ + 255) / 256, 256, 0, st>>>(x, xn1, hres, (long)S_ * H_);

    // ===== MoE =====
    rmsnorm_k<<<S_, 256, 0, st>>>(hres, wln2, xn2);

    gemmB_nn(xn2, Wgate, logits, S_, E_, H_, 1, 0, 0, 0, 1, st);
    topk_k<<<(S_ + 255) / 256, 256, 0, st>>>(logits, topi, coef);
    assign_k<<<E_, 256, 0, st>>>(topi, pos);

    zero_k<<<(int)(((long)E_ * CAP_ * H_ / 4 + 255) / 256), 256, 0, st>>>(buf, (long)E_ * CAP_ * H_ / 4);
    scatter_k<<<S_ * TOPK_, 256, 0, st>>>(xn2, topi, pos, buf);

    // expert up/gate: 64 x (256x1408, K=1024)
    gemmA(buf, Weg, gg, CAP_, ID_, H_, E_,
          (long)CAP_ * H_, (long)H_ * ID_, (long)CAP_ * ID_, 1, st);
    gemmA(buf, Weu, uu, CAP_, ID_, H_, E_,
          (long)CAP_ * H_, (long)H_ * ID_, (long)CAP_ * ID_, 1, st);

    {
        long n = (long)E_ * CAP_ * ID_;
        act_k<<<(int)((n + 255) / 256), 256, 0, st>>>(gg, uu, n);
    }

    // expert down: 64 x (256x1024, K=1408)
    gemmA(gg, Wed, yy, CAP_, H_, ID_, E_,
          (long)CAP_ * ID_, (long)ID_ * H_, (long)CAP_ * H_, 1, st);

    // shared expert
    gemmA(xn2, Wsg, sg, S_, ID_, H_, 1, 0, 0, 0, 1, st);
    gemmA(xn2, Wsu, su, S_, ID_, H_, 1, 0, 0, 0, 1, st);
    {
        long n = (long)S_ * ID_;
        act_k<<<(int)((n + 255) / 256), 256, 0, st>>>(sg, su, n);
    }
    gemmA(sg, Wsd, shb, S_, H_, ID_, 1, 0, 0, 0, 1, st);

    // gather + residuals
    final_k<<<S_, 256, 0, st>>>(hres, shb, yy, topi, pos, coef, out);
}